// round 1
// baseline (speedup 1.0000x reference)
#include <cuda_runtime.h>
#include <cuda_bf16.h>

// Problem constants
#define BB   2
#define SS   2048
#define EE   1024
#define HH   16
#define HKV  4
#define DD   64
#define KVE  (HKV * DD)   // 256
#define MM   (BB * SS)    // 4096

// Scratch (allocation-free rule: __device__ globals)
__device__ float g_Q[(size_t)MM * EE];    // 16 MB
__device__ float g_K[(size_t)MM * KVE];   // 4 MB
__device__ float g_V[(size_t)MM * KVE];   // 4 MB
__device__ float g_C[(size_t)MM * EE];    // 16 MB (attention context)

// ---------------------------------------------------------------------------
// SGEMM with bias: C[M,N] = A[M,K] @ W[N,K]^T + bias[N]
// 128x128 block tile, BK=8, 256 threads, 8x8 per-thread microtile.
// ---------------------------------------------------------------------------
__global__ __launch_bounds__(256) void sgemm_bias_kernel(
    const float* __restrict__ A, const float* __restrict__ W,
    const float* __restrict__ bias, float* __restrict__ C,
    int M, int N, int K)
{
    __shared__ float As[8][128];
    __shared__ float Bs[8][128];

    const int tid  = threadIdx.x;
    const int tx   = tid & 15;        // 0..15 -> col groups of 8
    const int ty   = tid >> 4;        // 0..15 -> row groups of 8
    const int row0 = blockIdx.y * 128;
    const int col0 = blockIdx.x * 128;

    const int lrow = tid >> 1;        // 0..127
    const int lseg = (tid & 1) * 4;   // 0 or 4

    const float* Ap = A + (size_t)(row0 + lrow) * K + lseg;
    const float* Wp = W + (size_t)(col0 + lrow) * K + lseg;

    float acc[8][8];
#pragma unroll
    for (int i = 0; i < 8; i++)
#pragma unroll
        for (int j = 0; j < 8; j++) acc[i][j] = 0.f;

    for (int k0 = 0; k0 < K; k0 += 8) {
        float4 a4 = *(const float4*)(Ap + k0);
        float4 b4 = *(const float4*)(Wp + k0);
        As[lseg + 0][lrow] = a4.x;
        As[lseg + 1][lrow] = a4.y;
        As[lseg + 2][lrow] = a4.z;
        As[lseg + 3][lrow] = a4.w;
        Bs[lseg + 0][lrow] = b4.x;
        Bs[lseg + 1][lrow] = b4.y;
        Bs[lseg + 2][lrow] = b4.z;
        Bs[lseg + 3][lrow] = b4.w;
        __syncthreads();

#pragma unroll
        for (int k = 0; k < 8; k++) {
            float a[8], b[8];
            *(float4*)&a[0] = *(const float4*)&As[k][ty * 8];
            *(float4*)&a[4] = *(const float4*)&As[k][ty * 8 + 4];
            *(float4*)&b[0] = *(const float4*)&Bs[k][tx * 8];
            *(float4*)&b[4] = *(const float4*)&Bs[k][tx * 8 + 4];
#pragma unroll
            for (int i = 0; i < 8; i++)
#pragma unroll
                for (int j = 0; j < 8; j++)
                    acc[i][j] = fmaf(a[i], b[j], acc[i][j]);
        }
        __syncthreads();
    }

    float bv[8];
#pragma unroll
    for (int j = 0; j < 8; j++) bv[j] = bias[col0 + tx * 8 + j];

#pragma unroll
    for (int i = 0; i < 8; i++) {
        int r = row0 + ty * 8 + i;
        float* cp = C + (size_t)r * N + col0 + tx * 8;
        float4 v0, v1;
        v0.x = acc[i][0] + bv[0]; v0.y = acc[i][1] + bv[1];
        v0.z = acc[i][2] + bv[2]; v0.w = acc[i][3] + bv[3];
        v1.x = acc[i][4] + bv[4]; v1.y = acc[i][5] + bv[5];
        v1.z = acc[i][6] + bv[6]; v1.w = acc[i][7] + bv[7];
        *(float4*)(cp)     = v0;
        *(float4*)(cp + 4) = v1;
    }
}

// ---------------------------------------------------------------------------
// Flash attention (causal, GQA). One thread owns one query row.
// Block: 128 q-rows, KV tile = 32 rows. Static shared < 48 KB.
// ---------------------------------------------------------------------------
#define FM 128
#define FN 32

__global__ __launch_bounds__(128) void flash_kernel(
    const float* __restrict__ Q, const float* __restrict__ K,
    const float* __restrict__ V, float* __restrict__ O)
{
    __shared__ float Ksh[FN][DD];        // 8 KB
    __shared__ float Vsh[FN][DD];        // 8 KB
    __shared__ float Ssh[FM][FN + 1];    // 16.9 KB (pad -> conflict-free)

    const int tid = threadIdx.x;
    // reversed order: heaviest (most causal work) blocks launch first
    const int mt  = gridDim.x - 1 - blockIdx.x;
    const int m0  = mt * FM;
    const int h   = blockIdx.y;
    const int b   = blockIdx.z;
    const int g   = h >> 2;            // kv head = h / REP
    const int qrow = m0 + tid;

    float4 q4[16], o4[16];
    const float* qp = Q + ((size_t)(b * SS + qrow)) * EE + h * DD;
#pragma unroll
    for (int t = 0; t < 16; t++) {
        q4[t] = *(const float4*)(qp + t * 4);
        o4[t] = make_float4(0.f, 0.f, 0.f, 0.f);
    }

    float m_i = -1e30f, l_i = 0.f;
    const int jend = m0 + FM;          // causal: only tiles with j0 <= max qrow

    for (int j0 = 0; j0 < jend; j0 += FN) {
        // cooperative load of K/V tile (coalesced float4)
        for (int f = tid; f < FN * (DD / 4); f += 128) {
            int j   = f >> 4;
            int seg = (f & 15) << 2;
            size_t off = ((size_t)(b * SS + j0 + j)) * KVE + g * DD + seg;
            *(float4*)(&Ksh[j][seg]) = *(const float4*)(K + off);
            *(float4*)(&Vsh[j][seg]) = *(const float4*)(V + off);
        }
        __syncthreads();

        // pass 1: scores for my row
        float tmax = -1e30f;
        float* srow = &Ssh[tid][0];
        for (int j = 0; j < FN; j++) {
            float s = -1e30f;
            if (j0 + j <= qrow) {
                const float4* kp4 = (const float4*)(&Ksh[j][0]);
                float acc = 0.f;
#pragma unroll
                for (int t = 0; t < 16; t++) {
                    float4 kk = kp4[t];
                    acc = fmaf(q4[t].x, kk.x, acc);
                    acc = fmaf(q4[t].y, kk.y, acc);
                    acc = fmaf(q4[t].z, kk.z, acc);
                    acc = fmaf(q4[t].w, kk.w, acc);
                }
                s = acc * 0.125f;   // 1/sqrt(64)
            }
            srow[j] = s;
            tmax = fmaxf(tmax, s);
        }

        // online softmax rescale
        float mnew = fmaxf(m_i, tmax);
        float corr = __expf(m_i - mnew);
        l_i *= corr;
#pragma unroll
        for (int t = 0; t < 16; t++) {
            o4[t].x *= corr; o4[t].y *= corr;
            o4[t].z *= corr; o4[t].w *= corr;
        }
        m_i = mnew;

        // pass 2: accumulate P @ V
        for (int j = 0; j < FN; j++) {
            float p = __expf(srow[j] - mnew);
            l_i += p;
            const float4* vp4 = (const float4*)(&Vsh[j][0]);
#pragma unroll
            for (int t = 0; t < 16; t++) {
                float4 vv = vp4[t];
                o4[t].x = fmaf(p, vv.x, o4[t].x);
                o4[t].y = fmaf(p, vv.y, o4[t].y);
                o4[t].z = fmaf(p, vv.z, o4[t].z);
                o4[t].w = fmaf(p, vv.w, o4[t].w);
            }
        }
        __syncthreads();
    }

    // ctx layout: [B, S, H*D] with channel = h*D + d (matches reference reshape)
    float inv = 1.f / l_i;
    float* op = O + ((size_t)(b * SS + qrow)) * EE + h * DD;
#pragma unroll
    for (int t = 0; t < 16; t++) {
        float4 w;
        w.x = o4[t].x * inv; w.y = o4[t].y * inv;
        w.z = o4[t].z * inv; w.w = o4[t].w * inv;
        *(float4*)(op + t * 4) = w;
    }
}

// ---------------------------------------------------------------------------
// Launch
// ---------------------------------------------------------------------------
extern "C" void kernel_launch(void* const* d_in, const int* in_sizes, int n_in,
                              void* d_out, int out_size)
{
    const float* x    = (const float*)d_in[0];
    // d_in[1] is the causal mask (triu, k=1). We apply it analytically (j<=i).
    const float* wq_w = (const float*)d_in[2];
    const float* wq_b = (const float*)d_in[3];
    const float* wk_w = (const float*)d_in[4];
    const float* wk_b = (const float*)d_in[5];
    const float* wv_w = (const float*)d_in[6];
    const float* wv_b = (const float*)d_in[7];
    const float* wo_w = (const float*)d_in[8];
    const float* wo_b = (const float*)d_in[9];
    float* out = (float*)d_out;

    float *Qp, *Kp, *Vp, *Cp;
    cudaGetSymbolAddress((void**)&Qp, g_Q);
    cudaGetSymbolAddress((void**)&Kp, g_K);
    cudaGetSymbolAddress((void**)&Vp, g_V);
    cudaGetSymbolAddress((void**)&Cp, g_C);

    dim3 blk(256);
    // Q / K / V projections
    sgemm_bias_kernel<<<dim3(EE / 128, MM / 128), blk>>>(x, wq_w, wq_b, Qp, MM, EE,  EE);
    sgemm_bias_kernel<<<dim3(KVE / 128, MM / 128), blk>>>(x, wk_w, wk_b, Kp, MM, KVE, EE);
    sgemm_bias_kernel<<<dim3(KVE / 128, MM / 128), blk>>>(x, wv_w, wv_b, Vp, MM, KVE, EE);

    // causal GQA flash attention
    flash_kernel<<<dim3(SS / FM, HH, BB), 128>>>(Qp, Kp, Vp, Cp);

    // output projection
    sgemm_bias_kernel<<<dim3(EE / 128, MM / 128), blk>>>(Cp, wo_w, wo_b, out, MM, EE, EE);
}

// round 3
// speedup vs baseline: 1.3813x; 1.3813x over previous
#include <cuda_runtime.h>
#include <cuda_bf16.h>
#include <cstdint>

// Problem constants
#define BB   2
#define SS   2048
#define EE   1024
#define HH   16
#define HKV  4
#define DD   64
#define KVE  (HKV * DD)   // 256
#define MM   (BB * SS)    // 4096

// Scratch (allocation-free rule: __device__ globals)
__device__ float g_Q[(size_t)MM * EE];    // 16 MB
__device__ float g_K[(size_t)MM * KVE];   // 4 MB
__device__ float g_V[(size_t)MM * KVE];   // 4 MB
__device__ float g_C[(size_t)MM * EE];    // 16 MB (attention context)

// ===========================================================================
// tf32 tensor-core GEMM (mma.sync.m16n8k8) with fused bias:
//   C[M,N] = A[M,K] @ W[N,K]^T + bias[N]
// 128x128 CTA tile, BK=32, 8 warps (2 x 4), warp tile 64x32,
// double-buffered SMEM with 36-float stride (conflict-free fragment loads).
// ===========================================================================
#define GBK   32
#define GLDA  36                       // BK + 4 pad -> bank = 4*g + tig
#define GBUF  (128 * GLDA)             // uints per (A or B) buffer
#define GSMEM (4 * GBUF * 4)           // A0,A1,B0,B1 = 73728 bytes

__device__ __forceinline__ uint32_t f2tf32(float x) {
    uint32_t u;
    asm("cvt.rna.tf32.f32 %0, %1;" : "=r"(u) : "f"(x));
    return u;
}

__device__ __forceinline__ void mma_tf32(float* c, const uint32_t* a,
                                         const uint32_t* b) {
    asm volatile(
        "mma.sync.aligned.m16n8k8.row.col.f32.tf32.tf32.f32 "
        "{%0,%1,%2,%3}, {%4,%5,%6,%7}, {%8,%9}, {%0,%1,%2,%3};"
        : "+f"(c[0]), "+f"(c[1]), "+f"(c[2]), "+f"(c[3])
        : "r"(a[0]), "r"(a[1]), "r"(a[2]), "r"(a[3]),
          "r"(b[0]), "r"(b[1]));
}

__device__ __forceinline__ void st_s4(uint32_t* p, float4 v) {
    asm volatile("st.shared.v4.b32 [%0], {%1,%2,%3,%4};"
                 :: "l"(p), "r"(f2tf32(v.x)), "r"(f2tf32(v.y)),
                    "r"(f2tf32(v.z)), "r"(f2tf32(v.w)) : "memory");
}

__global__ void __launch_bounds__(256)
gemm_tc(const float* __restrict__ A, const float* __restrict__ W,
        const float* __restrict__ bias, float* __restrict__ C,
        int M, int N, int K)
{
    extern __shared__ uint32_t sm[];
    uint32_t* As = sm;                 // [2][GBUF]
    uint32_t* Bs = sm + 2 * GBUF;      // [2][GBUF]

    const int tid  = threadIdx.x;
    const int row0 = blockIdx.y * 128;
    const int col0 = blockIdx.x * 128;

    // staging map: 2 threads per row, 16 floats each
    const int r    = tid >> 1;
    const int ksub = (tid & 1) * 16;
    const float* Ag = A + (size_t)(row0 + r) * K + ksub;
    const float* Wg = W + (size_t)(col0 + r) * K + ksub;

    // warp map: 2 (M) x 4 (N)
    const int lane = tid & 31;
    const int wid  = tid >> 5;
    const int wm   = (wid & 1) * 64;
    const int wn   = (wid >> 1) * 32;
    const int g    = lane >> 2;        // 0..7
    const int tig  = lane & 3;         // 0..3

    float acc[4][4][4];
#pragma unroll
    for (int mt = 0; mt < 4; mt++)
#pragma unroll
        for (int nt = 0; nt < 4; nt++)
#pragma unroll
            for (int i = 0; i < 4; i++) acc[mt][nt][i] = 0.f;

    // prologue: stage tile 0 into buffer 0
    {
        uint32_t* Ad = As + r * GLDA + ksub;
        uint32_t* Bd = Bs + r * GLDA + ksub;
#pragma unroll
        for (int i = 0; i < 4; i++) {
            st_s4(Ad + i * 4, *(const float4*)(Ag + i * 4));
            st_s4(Bd + i * 4, *(const float4*)(Wg + i * 4));
        }
    }
    __syncthreads();

    const int NI = K / GBK;
    float4 an[4], bn[4];
    for (int it = 0; it < NI; it++) {
        const int p = it & 1;
        const bool hn = (it + 1 < NI);
        if (hn) {
            const int kn = (it + 1) * GBK;
#pragma unroll
            for (int i = 0; i < 4; i++) {
                an[i] = *(const float4*)(Ag + kn + i * 4);
                bn[i] = *(const float4*)(Wg + kn + i * 4);
            }
        }

        const uint32_t* Ab = As + p * GBUF;
        const uint32_t* Bb = Bs + p * GBUF;
#pragma unroll
        for (int ks = 0; ks < 4; ks++) {
            uint32_t a[4][4], b[4][2];
#pragma unroll
            for (int mt = 0; mt < 4; mt++) {
                const uint32_t* ap = Ab + (wm + mt * 16 + g) * GLDA + ks * 8 + tig;
                a[mt][0] = ap[0];
                a[mt][1] = ap[8 * GLDA];
                a[mt][2] = ap[4];
                a[mt][3] = ap[8 * GLDA + 4];
            }
#pragma unroll
            for (int nt = 0; nt < 4; nt++) {
                const uint32_t* bp = Bb + (wn + nt * 8 + g) * GLDA + ks * 8 + tig;
                b[nt][0] = bp[0];
                b[nt][1] = bp[4];
            }
#pragma unroll
            for (int mt = 0; mt < 4; mt++)
#pragma unroll
                for (int nt = 0; nt < 4; nt++)
                    mma_tf32(acc[mt][nt], a[mt], b[nt]);
        }

        if (hn) {
            uint32_t* Ad = As + (1 - p) * GBUF + r * GLDA + ksub;
            uint32_t* Bd = Bs + (1 - p) * GBUF + r * GLDA + ksub;
#pragma unroll
            for (int i = 0; i < 4; i++) {
                st_s4(Ad + i * 4, an[i]);
                st_s4(Bd + i * 4, bn[i]);
            }
            __syncthreads();
        }
    }

    // epilogue: fragments -> global with fused bias
#pragma unroll
    for (int mt = 0; mt < 4; mt++) {
        const int rowa = row0 + wm + mt * 16 + g;
#pragma unroll
        for (int nt = 0; nt < 4; nt++) {
            const int cola = col0 + wn + nt * 8 + 2 * tig;
            const float2 bv = *(const float2*)(bias + cola);
            float2 v0, v1;
            v0.x = acc[mt][nt][0] + bv.x;
            v0.y = acc[mt][nt][1] + bv.y;
            v1.x = acc[mt][nt][2] + bv.x;
            v1.y = acc[mt][nt][3] + bv.y;
            *(float2*)(C + (size_t)rowa * N + cola)       = v0;
            *(float2*)(C + (size_t)(rowa + 8) * N + cola) = v1;
        }
    }
}

// ---------------------------------------------------------------------------
// Flash attention (causal, GQA). One thread owns one query row. (round-1 ver.)
// ---------------------------------------------------------------------------
#define FM 128
#define FN 32

__global__ __launch_bounds__(128) void flash_kernel(
    const float* __restrict__ Q, const float* __restrict__ K,
    const float* __restrict__ V, float* __restrict__ O)
{
    __shared__ float Ksh[FN][DD];
    __shared__ float Vsh[FN][DD];
    __shared__ float Ssh[FM][FN + 1];

    const int tid = threadIdx.x;
    const int mt  = gridDim.x - 1 - blockIdx.x;
    const int m0  = mt * FM;
    const int h   = blockIdx.y;
    const int b   = blockIdx.z;
    const int g   = h >> 2;
    const int qrow = m0 + tid;

    float4 q4[16], o4[16];
    const float* qp = Q + ((size_t)(b * SS + qrow)) * EE + h * DD;
#pragma unroll
    for (int t = 0; t < 16; t++) {
        q4[t] = *(const float4*)(qp + t * 4);
        o4[t] = make_float4(0.f, 0.f, 0.f, 0.f);
    }

    float m_i = -1e30f, l_i = 0.f;
    const int jend = m0 + FM;

    for (int j0 = 0; j0 < jend; j0 += FN) {
        for (int f = tid; f < FN * (DD / 4); f += 128) {
            int j   = f >> 4;
            int seg = (f & 15) << 2;
            size_t off = ((size_t)(b * SS + j0 + j)) * KVE + g * DD + seg;
            *(float4*)(&Ksh[j][seg]) = *(const float4*)(K + off);
            *(float4*)(&Vsh[j][seg]) = *(const float4*)(V + off);
        }
        __syncthreads();

        float tmax = -1e30f;
        float* srow = &Ssh[tid][0];
        for (int j = 0; j < FN; j++) {
            float s = -1e30f;
            if (j0 + j <= qrow) {
                const float4* kp4 = (const float4*)(&Ksh[j][0]);
                float acc = 0.f;
#pragma unroll
                for (int t = 0; t < 16; t++) {
                    float4 kk = kp4[t];
                    acc = fmaf(q4[t].x, kk.x, acc);
                    acc = fmaf(q4[t].y, kk.y, acc);
                    acc = fmaf(q4[t].z, kk.z, acc);
                    acc = fmaf(q4[t].w, kk.w, acc);
                }
                s = acc * 0.125f;
            }
            srow[j] = s;
            tmax = fmaxf(tmax, s);
        }

        float mnew = fmaxf(m_i, tmax);
        float corr = __expf(m_i - mnew);
        l_i *= corr;
#pragma unroll
        for (int t = 0; t < 16; t++) {
            o4[t].x *= corr; o4[t].y *= corr;
            o4[t].z *= corr; o4[t].w *= corr;
        }
        m_i = mnew;

        for (int j = 0; j < FN; j++) {
            float p = __expf(srow[j] - mnew);
            l_i += p;
            const float4* vp4 = (const float4*)(&Vsh[j][0]);
#pragma unroll
            for (int t = 0; t < 16; t++) {
                float4 vv = vp4[t];
                o4[t].x = fmaf(p, vv.x, o4[t].x);
                o4[t].y = fmaf(p, vv.y, o4[t].y);
                o4[t].z = fmaf(p, vv.z, o4[t].z);
                o4[t].w = fmaf(p, vv.w, o4[t].w);
            }
        }
        __syncthreads();
    }

    float inv = 1.f / l_i;
    float* op = O + ((size_t)(b * SS + qrow)) * EE + h * DD;
#pragma unroll
    for (int t = 0; t < 16; t++) {
        float4 w;
        w.x = o4[t].x * inv; w.y = o4[t].y * inv;
        w.z = o4[t].z * inv; w.w = o4[t].w * inv;
        *(float4*)(op + t * 4) = w;
    }
}

// ---------------------------------------------------------------------------
// Launch
// ---------------------------------------------------------------------------
extern "C" void kernel_launch(void* const* d_in, const int* in_sizes, int n_in,
                              void* d_out, int out_size)
{
    const float* x    = (const float*)d_in[0];
    // d_in[1] is the causal mask (triu, k=1) — applied analytically (j<=i).
    const float* wq_w = (const float*)d_in[2];
    const float* wq_b = (const float*)d_in[3];
    const float* wk_w = (const float*)d_in[4];
    const float* wk_b = (const float*)d_in[5];
    const float* wv_w = (const float*)d_in[6];
    const float* wv_b = (const float*)d_in[7];
    const float* wo_w = (const float*)d_in[8];
    const float* wo_b = (const float*)d_in[9];
    float* out = (float*)d_out;

    float *Qp, *Kp, *Vp, *Cp;
    cudaGetSymbolAddress((void**)&Qp, g_Q);
    cudaGetSymbolAddress((void**)&Kp, g_K);
    cudaGetSymbolAddress((void**)&Vp, g_V);
    cudaGetSymbolAddress((void**)&Cp, g_C);

    cudaFuncSetAttribute(gemm_tc,
                         cudaFuncAttributeMaxDynamicSharedMemorySize, GSMEM);

    // Q / K / V projections (tf32 tensor cores)
    gemm_tc<<<dim3(EE / 128,  MM / 128), 256, GSMEM>>>(x, wq_w, wq_b, Qp, MM, EE,  EE);
    gemm_tc<<<dim3(KVE / 128, MM / 128), 256, GSMEM>>>(x, wk_w, wk_b, Kp, MM, KVE, EE);
    gemm_tc<<<dim3(KVE / 128, MM / 128), 256, GSMEM>>>(x, wv_w, wv_b, Vp, MM, KVE, EE);

    // causal GQA flash attention (fp32)
    flash_kernel<<<dim3(SS / FM, HH, BB), 128>>>(Qp, Kp, Vp, Cp);

    // output projection (tf32 tensor cores)
    gemm_tc<<<dim3(EE / 128,  MM / 128), 256, GSMEM>>>(Cp, wo_w, wo_b, out, MM, EE, EE);
}

// round 4
// speedup vs baseline: 3.1516x; 2.2816x over previous
#include <cuda_runtime.h>
#include <cuda_bf16.h>
#include <cstdint>

// Problem constants
#define BB   2
#define SS   2048
#define EE   1024
#define HH   16
#define HKV  4
#define DD   64
#define KVE  (HKV * DD)   // 256
#define MM   (BB * SS)    // 4096

// Scratch (allocation-free rule: __device__ globals)
__device__ float g_Q[(size_t)MM * EE];    // 16 MB
__device__ float g_K[(size_t)MM * KVE];   // 4 MB
__device__ float g_V[(size_t)MM * KVE];   // 4 MB
__device__ float g_C[(size_t)MM * EE];    // 16 MB (attention context)

__device__ __forceinline__ uint32_t f2tf32(float x) {
    uint32_t u;
    asm("cvt.rna.tf32.f32 %0, %1;" : "=r"(u) : "f"(x));
    return u;
}

__device__ __forceinline__ void mma_tf32(float* c, const uint32_t* a,
                                         const uint32_t* b) {
    asm volatile(
        "mma.sync.aligned.m16n8k8.row.col.f32.tf32.tf32.f32 "
        "{%0,%1,%2,%3}, {%4,%5,%6,%7}, {%8,%9}, {%0,%1,%2,%3};"
        : "+f"(c[0]), "+f"(c[1]), "+f"(c[2]), "+f"(c[3])
        : "r"(a[0]), "r"(a[1]), "r"(a[2]), "r"(a[3]),
          "r"(b[0]), "r"(b[1]));
}

// ===========================================================================
// tf32 tensor-core GEMM (mma.sync.m16n8k8) with fused bias (round-3, passing)
// ===========================================================================
#define GBK   32
#define GLDA  36
#define GBUF  (128 * GLDA)
#define GSMEM (4 * GBUF * 4)

__device__ __forceinline__ void st_s4(uint32_t* p, float4 v) {
    asm volatile("st.shared.v4.b32 [%0], {%1,%2,%3,%4};"
                 :: "l"(p), "r"(f2tf32(v.x)), "r"(f2tf32(v.y)),
                    "r"(f2tf32(v.z)), "r"(f2tf32(v.w)) : "memory");
}

__global__ void __launch_bounds__(256)
gemm_tc(const float* __restrict__ A, const float* __restrict__ W,
        const float* __restrict__ bias, float* __restrict__ C,
        int M, int N, int K)
{
    extern __shared__ uint32_t sm[];
    uint32_t* As = sm;
    uint32_t* Bs = sm + 2 * GBUF;

    const int tid  = threadIdx.x;
    const int row0 = blockIdx.y * 128;
    const int col0 = blockIdx.x * 128;

    const int r    = tid >> 1;
    const int ksub = (tid & 1) * 16;
    const float* Ag = A + (size_t)(row0 + r) * K + ksub;
    const float* Wg = W + (size_t)(col0 + r) * K + ksub;

    const int lane = tid & 31;
    const int wid  = tid >> 5;
    const int wm   = (wid & 1) * 64;
    const int wn   = (wid >> 1) * 32;
    const int g    = lane >> 2;
    const int tig  = lane & 3;

    float acc[4][4][4];
#pragma unroll
    for (int mt = 0; mt < 4; mt++)
#pragma unroll
        for (int nt = 0; nt < 4; nt++)
#pragma unroll
            for (int i = 0; i < 4; i++) acc[mt][nt][i] = 0.f;

    {
        uint32_t* Ad = As + r * GLDA + ksub;
        uint32_t* Bd = Bs + r * GLDA + ksub;
#pragma unroll
        for (int i = 0; i < 4; i++) {
            st_s4(Ad + i * 4, *(const float4*)(Ag + i * 4));
            st_s4(Bd + i * 4, *(const float4*)(Wg + i * 4));
        }
    }
    __syncthreads();

    const int NI = K / GBK;
    float4 an[4], bn[4];
    for (int it = 0; it < NI; it++) {
        const int p = it & 1;
        const bool hn = (it + 1 < NI);
        if (hn) {
            const int kn = (it + 1) * GBK;
#pragma unroll
            for (int i = 0; i < 4; i++) {
                an[i] = *(const float4*)(Ag + kn + i * 4);
                bn[i] = *(const float4*)(Wg + kn + i * 4);
            }
        }

        const uint32_t* Ab = As + p * GBUF;
        const uint32_t* Bb = Bs + p * GBUF;
#pragma unroll
        for (int ks = 0; ks < 4; ks++) {
            uint32_t a[4][4], b[4][2];
#pragma unroll
            for (int mt = 0; mt < 4; mt++) {
                const uint32_t* ap = Ab + (wm + mt * 16 + g) * GLDA + ks * 8 + tig;
                a[mt][0] = ap[0];
                a[mt][1] = ap[8 * GLDA];
                a[mt][2] = ap[4];
                a[mt][3] = ap[8 * GLDA + 4];
            }
#pragma unroll
            for (int nt = 0; nt < 4; nt++) {
                const uint32_t* bp = Bb + (wn + nt * 8 + g) * GLDA + ks * 8 + tig;
                b[nt][0] = bp[0];
                b[nt][1] = bp[4];
            }
#pragma unroll
            for (int mt = 0; mt < 4; mt++)
#pragma unroll
                for (int nt = 0; nt < 4; nt++)
                    mma_tf32(acc[mt][nt], a[mt], b[nt]);
        }

        if (hn) {
            uint32_t* Ad = As + (1 - p) * GBUF + r * GLDA + ksub;
            uint32_t* Bd = Bs + (1 - p) * GBUF + r * GLDA + ksub;
#pragma unroll
            for (int i = 0; i < 4; i++) {
                st_s4(Ad + i * 4, an[i]);
                st_s4(Bd + i * 4, bn[i]);
            }
            __syncthreads();
        }
    }

#pragma unroll
    for (int mt = 0; mt < 4; mt++) {
        const int rowa = row0 + wm + mt * 16 + g;
#pragma unroll
        for (int nt = 0; nt < 4; nt++) {
            const int cola = col0 + wn + nt * 8 + 2 * tig;
            const float2 bv = *(const float2*)(bias + cola);
            float2 v0, v1;
            v0.x = acc[mt][nt][0] + bv.x;
            v0.y = acc[mt][nt][1] + bv.y;
            v1.x = acc[mt][nt][2] + bv.x;
            v1.y = acc[mt][nt][3] + bv.y;
            *(float2*)(C + (size_t)rowa * N + cola)       = v0;
            *(float2*)(C + (size_t)(rowa + 8) * N + cola) = v1;
        }
    }
}

// ===========================================================================
// Tensor-core flash attention (causal, GQA), tf32 mma.sync.
// CTA: 128 q-rows x 1 head x 1 batch. 8 warps x 16 q-rows. KV tile = 64.
// ===========================================================================
#define PLD 68   // P/Q smem stride (floats): A-frag reads bank 4g+tig (clean)
#define KLD 68   // K smem stride: B-frag reads bank 4g+tig (clean)
#define VLD 72   // V smem stride: B-frag reads bank 8tig+g (clean)
#define FSMEM ((128 * PLD + 64 * KLD + 64 * VLD) * 4)   // 70656 bytes

__global__ void __launch_bounds__(256, 2)
flash_tc(const float* __restrict__ Q, const float* __restrict__ K,
         const float* __restrict__ V, float* __restrict__ O)
{
    extern __shared__ uint32_t fsm[];
    uint32_t* Ps = fsm;                      // [128][PLD] (Q staging, then P)
    uint32_t* Ks = fsm + 128 * PLD;          // [64][KLD]
    uint32_t* Vs = Ks + 64 * KLD;            // [64][VLD]

    const int tid  = threadIdx.x;
    const int lane = tid & 31;
    const int wid  = tid >> 5;               // 0..7
    const int g    = lane >> 2;              // 0..7
    const int tig  = lane & 3;               // 0..3
    const int m0   = (gridDim.x - 1 - blockIdx.x) * 128;   // heavy-first
    const int h    = blockIdx.y;
    const int b    = blockIdx.z;
    const int kvh  = h >> 2;

    // stage Q (scaled by 1/8 = exact, tf32) into Ps
    {
        const int r  = tid >> 1;
        const int c0 = (tid & 1) * 32;
        const float* qg = Q + ((size_t)(b * SS + m0 + r)) * EE + h * DD + c0;
        uint32_t* dst = Ps + r * PLD + c0;
#pragma unroll
        for (int i = 0; i < 8; i++) {
            float4 v = *(const float4*)(qg + i * 4);
            dst[i * 4 + 0] = f2tf32(v.x * 0.125f);
            dst[i * 4 + 1] = f2tf32(v.y * 0.125f);
            dst[i * 4 + 2] = f2tf32(v.z * 0.125f);
            dst[i * 4 + 3] = f2tf32(v.w * 0.125f);
        }
    }
    __syncthreads();

    // pull Q A-fragments (held in registers for the whole kernel)
    uint32_t qa[8][4];
    {
        const uint32_t* base = Ps + (wid * 16 + g) * PLD;
#pragma unroll
        for (int ks = 0; ks < 8; ks++) {
            qa[ks][0] = base[ks * 8 + tig];
            qa[ks][1] = base[8 * PLD + ks * 8 + tig];
            qa[ks][2] = base[ks * 8 + tig + 4];
            qa[ks][3] = base[8 * PLD + ks * 8 + tig + 4];
        }
    }

    float oacc[8][4];
#pragma unroll
    for (int nt = 0; nt < 8; nt++)
#pragma unroll
        for (int i = 0; i < 4; i++) oacc[nt][i] = 0.f;
    float mrow[2] = { -1e30f, -1e30f };
    float lrow[2] = { 0.f, 0.f };

    const int r0 = m0 + wid * 16 + g;        // row of c0/c1 (c2/c3: r0+8)
    const int ntile = m0 / 64 + 2;

    for (int t = 0; t < ntile; t++) {
        const int j0 = t * 64;

        // cooperative K/V tile load (fp32 -> tf32)
        {
            const int r  = tid >> 2;
            const int cc = (tid & 3) * 16;
            const size_t off = ((size_t)(b * SS + j0 + r)) * KVE + kvh * DD + cc;
            const float* kg = K + off;
            const float* vg = V + off;
            uint32_t* kd = Ks + r * KLD + cc;
            uint32_t* vd = Vs + r * VLD + cc;
#pragma unroll
            for (int i = 0; i < 4; i++) {
                float4 a = *(const float4*)(kg + i * 4);
                float4 c = *(const float4*)(vg + i * 4);
                kd[i * 4 + 0] = f2tf32(a.x); kd[i * 4 + 1] = f2tf32(a.y);
                kd[i * 4 + 2] = f2tf32(a.z); kd[i * 4 + 3] = f2tf32(a.w);
                vd[i * 4 + 0] = f2tf32(c.x); vd[i * 4 + 1] = f2tf32(c.y);
                vd[i * 4 + 2] = f2tf32(c.z); vd[i * 4 + 3] = f2tf32(c.w);
            }
        }
        __syncthreads();

        const bool active = (j0 <= m0 + wid * 16 + 15);   // warp-uniform
        if (active) {
            // S = Q @ K^T
            float sc[8][4];
#pragma unroll
            for (int nt = 0; nt < 8; nt++)
#pragma unroll
                for (int i = 0; i < 4; i++) sc[nt][i] = 0.f;
#pragma unroll
            for (int ks = 0; ks < 8; ks++)
#pragma unroll
                for (int nt = 0; nt < 8; nt++) {
                    uint32_t bb[2];
                    const uint32_t* bp = Ks + (nt * 8 + g) * KLD + ks * 8 + tig;
                    bb[0] = bp[0];
                    bb[1] = bp[4];
                    mma_tf32(sc[nt], qa[ks], bb);
                }

            // causal mask (diagonal tiles only)
            if (j0 + 63 > r0) {
#pragma unroll
                for (int nt = 0; nt < 8; nt++) {
                    const int c = j0 + nt * 8 + 2 * tig;
                    if (c     > r0)     sc[nt][0] = -1e30f;
                    if (c + 1 > r0)     sc[nt][1] = -1e30f;
                    if (c     > r0 + 8) sc[nt][2] = -1e30f;
                    if (c + 1 > r0 + 8) sc[nt][3] = -1e30f;
                }
            }

            // row max (quad reduce)
            float tm0 = -1e30f, tm1 = -1e30f;
#pragma unroll
            for (int nt = 0; nt < 8; nt++) {
                tm0 = fmaxf(tm0, fmaxf(sc[nt][0], sc[nt][1]));
                tm1 = fmaxf(tm1, fmaxf(sc[nt][2], sc[nt][3]));
            }
            tm0 = fmaxf(tm0, __shfl_xor_sync(0xffffffffu, tm0, 1));
            tm0 = fmaxf(tm0, __shfl_xor_sync(0xffffffffu, tm0, 2));
            tm1 = fmaxf(tm1, __shfl_xor_sync(0xffffffffu, tm1, 1));
            tm1 = fmaxf(tm1, __shfl_xor_sync(0xffffffffu, tm1, 2));

            const float mn0 = fmaxf(mrow[0], tm0);
            const float mn1 = fmaxf(mrow[1], tm1);
            const float cr0 = __expf(mrow[0] - mn0);
            const float cr1 = __expf(mrow[1] - mn1);
            mrow[0] = mn0; mrow[1] = mn1;

            // exp + partial row sums (quad-reduced at the end)
            float ls0 = 0.f, ls1 = 0.f;
#pragma unroll
            for (int nt = 0; nt < 8; nt++) {
                sc[nt][0] = __expf(sc[nt][0] - mn0); ls0 += sc[nt][0];
                sc[nt][1] = __expf(sc[nt][1] - mn0); ls0 += sc[nt][1];
                sc[nt][2] = __expf(sc[nt][2] - mn1); ls1 += sc[nt][2];
                sc[nt][3] = __expf(sc[nt][3] - mn1); ls1 += sc[nt][3];
            }
            lrow[0] = lrow[0] * cr0 + ls0;
            lrow[1] = lrow[1] * cr1 + ls1;
#pragma unroll
            for (int nt = 0; nt < 8; nt++) {
                oacc[nt][0] *= cr0; oacc[nt][1] *= cr0;
                oacc[nt][2] *= cr1; oacc[nt][3] *= cr1;
            }

            // P -> smem (tf32), warp-private rows
            uint32_t* pr = Ps + (wid * 16 + g) * PLD;
#pragma unroll
            for (int nt = 0; nt < 8; nt++) {
                uint2 w0, w1;
                w0.x = f2tf32(sc[nt][0]); w0.y = f2tf32(sc[nt][1]);
                w1.x = f2tf32(sc[nt][2]); w1.y = f2tf32(sc[nt][3]);
                *(uint2*)(pr + nt * 8 + 2 * tig)           = w0;
                *(uint2*)(pr + 8 * PLD + nt * 8 + 2 * tig) = w1;
            }
            __syncwarp();

            // O += P @ V
#pragma unroll
            for (int ks = 0; ks < 8; ks++) {
                uint32_t pa[4];
                pa[0] = pr[ks * 8 + tig];
                pa[1] = pr[8 * PLD + ks * 8 + tig];
                pa[2] = pr[ks * 8 + tig + 4];
                pa[3] = pr[8 * PLD + ks * 8 + tig + 4];
#pragma unroll
                for (int nt = 0; nt < 8; nt++) {
                    uint32_t bb[2];
                    bb[0] = Vs[(ks * 8 + tig) * VLD + nt * 8 + g];
                    bb[1] = Vs[(ks * 8 + tig + 4) * VLD + nt * 8 + g];
                    mma_tf32(oacc[nt], pa, bb);
                }
            }
        }
        __syncthreads();
    }

    // finalize: quad-reduce l, normalize, store
    lrow[0] += __shfl_xor_sync(0xffffffffu, lrow[0], 1);
    lrow[0] += __shfl_xor_sync(0xffffffffu, lrow[0], 2);
    lrow[1] += __shfl_xor_sync(0xffffffffu, lrow[1], 1);
    lrow[1] += __shfl_xor_sync(0xffffffffu, lrow[1], 2);
    const float inv0 = 1.f / lrow[0];
    const float inv1 = 1.f / lrow[1];

    float* og = O + ((size_t)(b * SS + r0)) * EE + h * DD;
#pragma unroll
    for (int nt = 0; nt < 8; nt++) {
        float2 v0, v1;
        v0.x = oacc[nt][0] * inv0; v0.y = oacc[nt][1] * inv0;
        v1.x = oacc[nt][2] * inv1; v1.y = oacc[nt][3] * inv1;
        *(float2*)(og + nt * 8 + 2 * tig)            = v0;
        *(float2*)(og + (size_t)8 * EE + nt * 8 + 2 * tig) = v1;
    }
}

// ---------------------------------------------------------------------------
// Launch
// ---------------------------------------------------------------------------
extern "C" void kernel_launch(void* const* d_in, const int* in_sizes, int n_in,
                              void* d_out, int out_size)
{
    const float* x    = (const float*)d_in[0];
    // d_in[1] is the causal mask (triu, k=1) — applied analytically (j<=i).
    const float* wq_w = (const float*)d_in[2];
    const float* wq_b = (const float*)d_in[3];
    const float* wk_w = (const float*)d_in[4];
    const float* wk_b = (const float*)d_in[5];
    const float* wv_w = (const float*)d_in[6];
    const float* wv_b = (const float*)d_in[7];
    const float* wo_w = (const float*)d_in[8];
    const float* wo_b = (const float*)d_in[9];
    float* out = (float*)d_out;

    float *Qp, *Kp, *Vp, *Cp;
    cudaGetSymbolAddress((void**)&Qp, g_Q);
    cudaGetSymbolAddress((void**)&Kp, g_K);
    cudaGetSymbolAddress((void**)&Vp, g_V);
    cudaGetSymbolAddress((void**)&Cp, g_C);

    cudaFuncSetAttribute(gemm_tc,
                         cudaFuncAttributeMaxDynamicSharedMemorySize, GSMEM);
    cudaFuncSetAttribute(flash_tc,
                         cudaFuncAttributeMaxDynamicSharedMemorySize, FSMEM);

    // Q / K / V projections (tf32 tensor cores)
    gemm_tc<<<dim3(EE / 128,  MM / 128), 256, GSMEM>>>(x, wq_w, wq_b, Qp, MM, EE,  EE);
    gemm_tc<<<dim3(KVE / 128, MM / 128), 256, GSMEM>>>(x, wk_w, wk_b, Kp, MM, KVE, EE);
    gemm_tc<<<dim3(KVE / 128, MM / 128), 256, GSMEM>>>(x, wv_w, wv_b, Vp, MM, KVE, EE);

    // causal GQA flash attention (tf32 tensor cores)
    flash_tc<<<dim3(SS / 128, HH, BB), 256, FSMEM>>>(Qp, Kp, Vp, Cp);

    // output projection (tf32 tensor cores)
    gemm_tc<<<dim3(EE / 128,  MM / 128), 256, GSMEM>>>(Cp, wo_w, wo_b, out, MM, EE, EE);
}

// round 5
// speedup vs baseline: 3.5856x; 1.1377x over previous
#include <cuda_runtime.h>
#include <cuda_bf16.h>
#include <cstdint>

// Problem constants
#define BB   2
#define SS   2048
#define EE   1024
#define HH   16
#define HKV  4
#define DD   64
#define KVE  (HKV * DD)   // 256
#define MM   (BB * SS)    // 4096

// Scratch (allocation-free rule: __device__ globals)
__device__ float g_Q[(size_t)MM * EE];
__device__ float g_K[(size_t)MM * KVE];
__device__ float g_V[(size_t)MM * KVE];
__device__ float g_C[(size_t)MM * EE];

__device__ __forceinline__ uint32_t f2tf32(float x) {
    uint32_t u;
    asm("cvt.rna.tf32.f32 %0, %1;" : "=r"(u) : "f"(x));
    return u;
}
__device__ __forceinline__ void mma_tf32(float* c, const uint32_t* a,
                                         const uint32_t* b) {
    asm volatile(
        "mma.sync.aligned.m16n8k8.row.col.f32.tf32.tf32.f32 "
        "{%0,%1,%2,%3}, {%4,%5,%6,%7}, {%8,%9}, {%0,%1,%2,%3};"
        : "+f"(c[0]), "+f"(c[1]), "+f"(c[2]), "+f"(c[3])
        : "r"(a[0]), "r"(a[1]), "r"(a[2]), "r"(a[3]),
          "r"(b[0]), "r"(b[1]));
}
__device__ __forceinline__ void cp16(uint32_t d, const void* s) {
    asm volatile("cp.async.cg.shared.global [%0], [%1], 16;"
                 :: "r"(d), "l"(s) : "memory");
}
__device__ __forceinline__ void cp_commit() {
    asm volatile("cp.async.commit_group;" ::: "memory");
}
__device__ __forceinline__ void cp_wait0() {
    asm volatile("cp.async.wait_group 0;" ::: "memory");
}
__device__ __forceinline__ void cp_wait1() {
    asm volatile("cp.async.wait_group 1;" ::: "memory");
}
__device__ __forceinline__ uint32_t cvta_s(const void* p) {
    return (uint32_t)__cvta_generic_to_shared(p);
}

// ===========================================================================
// tf32 tensor-core GEMM core (cp.async double-buffered, fused bias)
//   C[.,cola] = A[M,1024] @ W^T + bias   (pointers pre-offset to the col tile)
// ===========================================================================
#define GBK   32
#define GLDA  36
#define GBUF  (128 * GLDA)           // floats per buffer
#define GSMEM (4 * GBUF * 4)         // A0 A1 B0 B1 = 73728 bytes

__device__ __forceinline__ void gemm_core(
    const float* __restrict__ A, const float* __restrict__ W,
    const float* __restrict__ bias, float* __restrict__ C,
    int Nc, int row0)
{
    extern __shared__ float sm[];
    float* As = sm;                  // [2][GBUF]
    float* Bs = sm + 2 * GBUF;       // [2][GBUF]

    const int tid  = threadIdx.x;
    const int K    = EE;

    const int r    = tid >> 1;
    const int ksub = (tid & 1) * 16;
    const float* Ag = A + (size_t)(row0 + r) * K + ksub;
    const float* Wg = W + (size_t)r * K + ksub;
    const uint32_t Asd = cvta_s(As + r * GLDA + ksub);
    const uint32_t Bsd = cvta_s(Bs + r * GLDA + ksub);

    const int lane = tid & 31;
    const int wid  = tid >> 5;
    const int wm   = (wid & 1) * 64;
    const int wn   = (wid >> 1) * 32;
    const int g    = lane >> 2;
    const int tig  = lane & 3;

    float acc[4][4][4];
#pragma unroll
    for (int mt = 0; mt < 4; mt++)
#pragma unroll
        for (int nt = 0; nt < 4; nt++)
#pragma unroll
            for (int i = 0; i < 4; i++) acc[mt][nt][i] = 0.f;

    // prologue: stage k-chunk 0 into buffer 0
#pragma unroll
    for (int i = 0; i < 4; i++) {
        cp16(Asd + i * 16, Ag + i * 4);
        cp16(Bsd + i * 16, Wg + i * 4);
    }
    cp_commit();

    const int NI = K / GBK;          // 32
    for (int it = 0; it < NI; it++) {
        const int p = it & 1;
        if (it + 1 < NI) {
            const float* a = Ag + (it + 1) * GBK;
            const float* w = Wg + (it + 1) * GBK;
            const uint32_t ad = Asd + (1 - p) * GBUF * 4;
            const uint32_t bd = Bsd + (1 - p) * GBUF * 4;
#pragma unroll
            for (int i = 0; i < 4; i++) {
                cp16(ad + i * 16, a + i * 4);
                cp16(bd + i * 16, w + i * 4);
            }
            cp_commit();
            cp_wait1();
        } else {
            cp_wait0();
        }
        __syncthreads();

        const float* Ab = As + p * GBUF;
        const float* Bb = Bs + p * GBUF;
#pragma unroll
        for (int ks = 0; ks < 4; ks++) {
            uint32_t a[4][4], b[4][2];
#pragma unroll
            for (int mt = 0; mt < 4; mt++) {
                const float* ap = Ab + (wm + mt * 16 + g) * GLDA + ks * 8 + tig;
                a[mt][0] = f2tf32(ap[0]);
                a[mt][1] = f2tf32(ap[8 * GLDA]);
                a[mt][2] = f2tf32(ap[4]);
                a[mt][3] = f2tf32(ap[8 * GLDA + 4]);
            }
#pragma unroll
            for (int nt = 0; nt < 4; nt++) {
                const float* bp = Bb + (wn + nt * 8 + g) * GLDA + ks * 8 + tig;
                b[nt][0] = f2tf32(bp[0]);
                b[nt][1] = f2tf32(bp[4]);
            }
#pragma unroll
            for (int mt = 0; mt < 4; mt++)
#pragma unroll
                for (int nt = 0; nt < 4; nt++)
                    mma_tf32(acc[mt][nt], a[mt], b[nt]);
        }
        __syncthreads();
    }

    // epilogue: fused bias, direct stores
#pragma unroll
    for (int mt = 0; mt < 4; mt++) {
        const int rowa = row0 + wm + mt * 16 + g;
#pragma unroll
        for (int nt = 0; nt < 4; nt++) {
            const int cola = wn + nt * 8 + 2 * tig;
            const float2 bv = *(const float2*)(bias + cola);
            float2 v0, v1;
            v0.x = acc[mt][nt][0] + bv.x;
            v0.y = acc[mt][nt][1] + bv.y;
            v1.x = acc[mt][nt][2] + bv.x;
            v1.y = acc[mt][nt][3] + bv.y;
            *(float2*)(C + (size_t)rowa * Nc + cola)       = v0;
            *(float2*)(C + (size_t)(rowa + 8) * Nc + cola) = v1;
        }
    }
}

// fused Q/K/V projection: tiles 0-7 -> Q, 8-9 -> K, 10-11 -> V
__global__ void __launch_bounds__(256, 2)
gemm_qkv(const float* __restrict__ x,
         const float* __restrict__ wq, const float* __restrict__ bq, float* Qo,
         const float* __restrict__ wk, const float* __restrict__ bk, float* Ko,
         const float* __restrict__ wv, const float* __restrict__ bv, float* Vo)
{
    const int bx   = blockIdx.x;
    const int row0 = blockIdx.y * 128;
    const float *W, *bias;
    float* C;
    int Nc, c0;
    if (bx < 8)       { W = wq; bias = bq; C = Qo; Nc = EE;  c0 = bx * 128; }
    else if (bx < 10) { W = wk; bias = bk; C = Ko; Nc = KVE; c0 = (bx - 8) * 128; }
    else              { W = wv; bias = bv; C = Vo; Nc = KVE; c0 = (bx - 10) * 128; }
    gemm_core(x, W + (size_t)c0 * EE, bias + c0, C + c0, Nc, row0);
}

__global__ void __launch_bounds__(256, 2)
gemm_single(const float* __restrict__ A, const float* __restrict__ W,
            const float* __restrict__ bias, float* __restrict__ C)
{
    const int c0 = blockIdx.x * 128;
    gemm_core(A, W + (size_t)c0 * EE, bias + c0, C + c0, EE, blockIdx.y * 128);
}

// ===========================================================================
// Tensor-core flash attention (causal, GQA), tf32 mma.sync.
// cp.async double-buffered K/V (raw fp32), cvt at fragment load.
// CTA: 128 q-rows; 8 warps x 16 q-rows; KV tile = 64.
// ===========================================================================
#define PLD 68
#define KLD 68
#define VLD 72
#define FKB (64 * KLD)               // floats per K buffer
#define FVB (64 * VLD)               // floats per V buffer
#define FSMEM ((128 * PLD + 2 * FKB + 2 * FVB) * 4)   // 106496 bytes

__global__ void __launch_bounds__(256, 2)
flash_tc(const float* __restrict__ Q, const float* __restrict__ K,
         const float* __restrict__ V, float* __restrict__ O)
{
    extern __shared__ float fsm[];
    float* Ps = fsm;                 // [128][PLD]: Q raw fp32, then P tf32 bits
    float* Kb = fsm + 128 * PLD;     // [2][64][KLD] raw fp32
    float* Vb = Kb + 2 * FKB;        // [2][64][VLD] raw fp32

    const int tid  = threadIdx.x;
    const int lane = tid & 31;
    const int wid  = tid >> 5;
    const int g    = lane >> 2;
    const int tig  = lane & 3;
    const int m0   = (gridDim.x - 1 - blockIdx.x) * 128;   // heavy-first
    const int h    = blockIdx.y;
    const int b    = blockIdx.z;
    const int kvh  = h >> 2;

    // staging coords (row sr of the KV tile, 16-float chunk sc4)
    const int sr  = tid >> 2;
    const int sc4 = (tid & 3) * 16;
    const float* kgb = K + ((size_t)(b * SS + sr)) * KVE + kvh * DD + sc4;
    const float* vgb = V + ((size_t)(b * SS + sr)) * KVE + kvh * DD + sc4;
    const uint32_t kd0 = cvta_s(Kb + sr * KLD + sc4);
    const uint32_t vd0 = cvta_s(Vb + sr * VLD + sc4);

    // stage Q (scaled by 1/8, raw fp32)
    {
        const int r  = tid >> 1;
        const int c0 = (tid & 1) * 32;
        const float* qg = Q + ((size_t)(b * SS + m0 + r)) * EE + h * DD + c0;
        float* dst = Ps + r * PLD + c0;
#pragma unroll
        for (int i = 0; i < 8; i++) {
            float4 v = *(const float4*)(qg + i * 4);
            dst[i * 4 + 0] = v.x * 0.125f;
            dst[i * 4 + 1] = v.y * 0.125f;
            dst[i * 4 + 2] = v.z * 0.125f;
            dst[i * 4 + 3] = v.w * 0.125f;
        }
    }

    const int ntile = m0 / 64 + 2;

    // prologue: stage KV tile 0 into buffer 0
#pragma unroll
    for (int i = 0; i < 4; i++) {
        cp16(kd0 + i * 16, kgb + i * 4);
        cp16(vd0 + i * 16, vgb + i * 4);
    }
    cp_commit();
    __syncthreads();                 // Q visible

    // pull Q A-fragments (cvt once, held in regs)
    uint32_t qa[8][4];
    {
        const float* base = Ps + (wid * 16 + g) * PLD;
#pragma unroll
        for (int ks = 0; ks < 8; ks++) {
            qa[ks][0] = f2tf32(base[ks * 8 + tig]);
            qa[ks][1] = f2tf32(base[8 * PLD + ks * 8 + tig]);
            qa[ks][2] = f2tf32(base[ks * 8 + tig + 4]);
            qa[ks][3] = f2tf32(base[8 * PLD + ks * 8 + tig + 4]);
        }
    }

    float oacc[8][4];
#pragma unroll
    for (int nt = 0; nt < 8; nt++)
#pragma unroll
        for (int i = 0; i < 4; i++) oacc[nt][i] = 0.f;
    float mrow[2] = { -1e30f, -1e30f };
    float lrow[2] = { 0.f, 0.f };

    const int r0 = m0 + wid * 16 + g;

    for (int t = 0; t < ntile; t++) {
        const int cb = t & 1;
        if (t + 1 < ntile) {
            const float* kg = kgb + (size_t)((t + 1) * 64) * KVE;
            const float* vg = vgb + (size_t)((t + 1) * 64) * KVE;
            const uint32_t kd = kd0 + (1 - cb) * FKB * 4;
            const uint32_t vd = vd0 + (1 - cb) * FVB * 4;
#pragma unroll
            for (int i = 0; i < 4; i++) {
                cp16(kd + i * 16, kg + i * 4);
                cp16(vd + i * 16, vg + i * 4);
            }
            cp_commit();
            cp_wait1();
        } else {
            cp_wait0();
        }
        __syncthreads();

        const int j0 = t * 64;
        const bool active = (j0 <= m0 + wid * 16 + 15);    // warp-uniform
        if (active) {
            const float* Kc = Kb + cb * FKB;
            const float* Vc = Vb + cb * FVB;

            // S = Q @ K^T
            float sc[8][4];
#pragma unroll
            for (int nt = 0; nt < 8; nt++)
#pragma unroll
                for (int i = 0; i < 4; i++) sc[nt][i] = 0.f;
#pragma unroll
            for (int ks = 0; ks < 8; ks++)
#pragma unroll
                for (int nt = 0; nt < 8; nt++) {
                    uint32_t bb[2];
                    const float* bp = Kc + (nt * 8 + g) * KLD + ks * 8 + tig;
                    bb[0] = f2tf32(bp[0]);
                    bb[1] = f2tf32(bp[4]);
                    mma_tf32(sc[nt], qa[ks], bb);
                }

            // causal mask (diagonal tiles only)
            if (j0 + 63 > r0) {
#pragma unroll
                for (int nt = 0; nt < 8; nt++) {
                    const int c = j0 + nt * 8 + 2 * tig;
                    if (c     > r0)     sc[nt][0] = -1e30f;
                    if (c + 1 > r0)     sc[nt][1] = -1e30f;
                    if (c     > r0 + 8) sc[nt][2] = -1e30f;
                    if (c + 1 > r0 + 8) sc[nt][3] = -1e30f;
                }
            }

            // row max (quad reduce)
            float tm0 = -1e30f, tm1 = -1e30f;
#pragma unroll
            for (int nt = 0; nt < 8; nt++) {
                tm0 = fmaxf(tm0, fmaxf(sc[nt][0], sc[nt][1]));
                tm1 = fmaxf(tm1, fmaxf(sc[nt][2], sc[nt][3]));
            }
            tm0 = fmaxf(tm0, __shfl_xor_sync(0xffffffffu, tm0, 1));
            tm0 = fmaxf(tm0, __shfl_xor_sync(0xffffffffu, tm0, 2));
            tm1 = fmaxf(tm1, __shfl_xor_sync(0xffffffffu, tm1, 1));
            tm1 = fmaxf(tm1, __shfl_xor_sync(0xffffffffu, tm1, 2));

            const float mn0 = fmaxf(mrow[0], tm0);
            const float mn1 = fmaxf(mrow[1], tm1);
            const float cr0 = __expf(mrow[0] - mn0);
            const float cr1 = __expf(mrow[1] - mn1);
            mrow[0] = mn0; mrow[1] = mn1;

            float ls0 = 0.f, ls1 = 0.f;
#pragma unroll
            for (int nt = 0; nt < 8; nt++) {
                sc[nt][0] = __expf(sc[nt][0] - mn0); ls0 += sc[nt][0];
                sc[nt][1] = __expf(sc[nt][1] - mn0); ls0 += sc[nt][1];
                sc[nt][2] = __expf(sc[nt][2] - mn1); ls1 += sc[nt][2];
                sc[nt][3] = __expf(sc[nt][3] - mn1); ls1 += sc[nt][3];
            }
            lrow[0] = lrow[0] * cr0 + ls0;
            lrow[1] = lrow[1] * cr1 + ls1;
#pragma unroll
            for (int nt = 0; nt < 8; nt++) {
                oacc[nt][0] *= cr0; oacc[nt][1] *= cr0;
                oacc[nt][2] *= cr1; oacc[nt][3] *= cr1;
            }

            // P -> smem (tf32 bits), warp-private rows
            uint32_t* pr = (uint32_t*)(Ps + (wid * 16 + g) * PLD);
#pragma unroll
            for (int nt = 0; nt < 8; nt++) {
                uint2 w0, w1;
                w0.x = f2tf32(sc[nt][0]); w0.y = f2tf32(sc[nt][1]);
                w1.x = f2tf32(sc[nt][2]); w1.y = f2tf32(sc[nt][3]);
                *(uint2*)(pr + nt * 8 + 2 * tig)           = w0;
                *(uint2*)(pr + 8 * PLD + nt * 8 + 2 * tig) = w1;
            }
            __syncwarp();

            // O += P @ V
#pragma unroll
            for (int ks = 0; ks < 8; ks++) {
                uint32_t pa[4];
                pa[0] = pr[ks * 8 + tig];
                pa[1] = pr[8 * PLD + ks * 8 + tig];
                pa[2] = pr[ks * 8 + tig + 4];
                pa[3] = pr[8 * PLD + ks * 8 + tig + 4];
#pragma unroll
                for (int nt = 0; nt < 8; nt++) {
                    uint32_t bb[2];
                    bb[0] = f2tf32(Vc[(ks * 8 + tig) * VLD + nt * 8 + g]);
                    bb[1] = f2tf32(Vc[(ks * 8 + tig + 4) * VLD + nt * 8 + g]);
                    mma_tf32(oacc[nt], pa, bb);
                }
            }
        }
        __syncthreads();
    }

    // finalize
    lrow[0] += __shfl_xor_sync(0xffffffffu, lrow[0], 1);
    lrow[0] += __shfl_xor_sync(0xffffffffu, lrow[0], 2);
    lrow[1] += __shfl_xor_sync(0xffffffffu, lrow[1], 1);
    lrow[1] += __shfl_xor_sync(0xffffffffu, lrow[1], 2);
    const float inv0 = 1.f / lrow[0];
    const float inv1 = 1.f / lrow[1];

    float* og = O + ((size_t)(b * SS + r0)) * EE + h * DD;
#pragma unroll
    for (int nt = 0; nt < 8; nt++) {
        float2 v0, v1;
        v0.x = oacc[nt][0] * inv0; v0.y = oacc[nt][1] * inv0;
        v1.x = oacc[nt][2] * inv1; v1.y = oacc[nt][3] * inv1;
        *(float2*)(og + nt * 8 + 2 * tig)                  = v0;
        *(float2*)(og + (size_t)8 * EE + nt * 8 + 2 * tig) = v1;
    }
}

// ---------------------------------------------------------------------------
// Launch
// ---------------------------------------------------------------------------
extern "C" void kernel_launch(void* const* d_in, const int* in_sizes, int n_in,
                              void* d_out, int out_size)
{
    const float* x    = (const float*)d_in[0];
    // d_in[1] is the causal mask (triu, k=1) — applied analytically (j<=i).
    const float* wq_w = (const float*)d_in[2];
    const float* wq_b = (const float*)d_in[3];
    const float* wk_w = (const float*)d_in[4];
    const float* wk_b = (const float*)d_in[5];
    const float* wv_w = (const float*)d_in[6];
    const float* wv_b = (const float*)d_in[7];
    const float* wo_w = (const float*)d_in[8];
    const float* wo_b = (const float*)d_in[9];
    float* out = (float*)d_out;

    float *Qp, *Kp, *Vp, *Cp;
    cudaGetSymbolAddress((void**)&Qp, g_Q);
    cudaGetSymbolAddress((void**)&Kp, g_K);
    cudaGetSymbolAddress((void**)&Vp, g_V);
    cudaGetSymbolAddress((void**)&Cp, g_C);

    cudaFuncSetAttribute(gemm_qkv,
                         cudaFuncAttributeMaxDynamicSharedMemorySize, GSMEM);
    cudaFuncSetAttribute(gemm_single,
                         cudaFuncAttributeMaxDynamicSharedMemorySize, GSMEM);
    cudaFuncSetAttribute(flash_tc,
                         cudaFuncAttributeMaxDynamicSharedMemorySize, FSMEM);

    // fused Q/K/V projections
    gemm_qkv<<<dim3(12, MM / 128), 256, GSMEM>>>(
        x, wq_w, wq_b, Qp, wk_w, wk_b, Kp, wv_w, wv_b, Vp);

    // causal GQA flash attention
    flash_tc<<<dim3(SS / 128, HH, BB), 256, FSMEM>>>(Qp, Kp, Vp, Cp);

    // output projection
    gemm_single<<<dim3(EE / 128, MM / 128), 256, GSMEM>>>(Cp, wo_w, wo_b, out);
}